// round 9
// baseline (speedup 1.0000x reference)
#include <cuda_runtime.h>
#include <cuda_fp16.h>
#include <cstdint>

// ---------------- problem constants ----------------
#define B_      32
#define L_      32768
#define KW      16
#define D_      128
#define STRIDE_ 8
#define P_      4095
#define NCH     16           // K chunks (32 fp32 each, total 512)
#define NST     8            // stages (2 chunks each)

// ---------------- smem layout (bytes) ----------------
// ring: A[buf][c2] 8KB frags, B[buf][c2] 8KB frags (double buffered)
// PE table fp32 [128p][132 stride], smed, cb
#define OFF_A(buf, c2) ((buf) * 16384 + (c2) * 8192)
#define OFF_B(buf, c2) (32768 + (buf) * 16384 + (c2) * 8192)
#define OFF_PE   65536
#define PE_STRIDE 132
#define OFF_SMED (OFF_PE + 128 * PE_STRIDE * 4)      // 133120
#define OFF_CB   (OFF_SMED + 512)                    // 133632
#define SM_TOTAL (OFF_CB + 512)                      // 134144

// ---------------- precomputed W fragments (fp16) ----------------
// layout: [chunk(16)][ks(2)][ntpair(8)][lane(32)][4 u32]  (u32 = fp16x2)
__device__ uint32_t g_Bh[NCH * 2048];

__global__ void prep_w_kernel(const float* __restrict__ w) {
    int idx = blockIdx.x * 256 + threadIdx.x;       // 0..32767
    int r    = idx & 3;
    int lane = (idx >> 2) & 31;
    int ntp  = (idx >> 7) & 7;
    int ks   = (idx >> 10) & 1;
    int ci   = idx >> 11;
    int nt   = ntp * 2 + (r >> 1);
    int breg = r & 1;
    int n = nt * 8 + (lane >> 2);                   // d row
    int c = ci * 32 + ks * 16 + breg * 8 + 2 * (lane & 3);
    int m0 = c & 31, kk = c >> 5;                   // c = kk*32 + m
    float v0 = w[n * 512 + m0 * 16 + kk];
    float v1 = w[n * 512 + (m0 + 1) * 16 + kk];
    __half2 h = __floats2half2_rn(v0, v1);
    g_Bh[idx] = *(uint32_t*)&h;
}

// ---------------- mma wrapper (fp16) ----------------
__device__ __forceinline__ void mma_f16(float* c, uint4 a, uint32_t b0, uint32_t b1) {
    asm volatile(
        "mma.sync.aligned.m16n8k16.row.col.f32.f16.f16.f32 "
        "{%0,%1,%2,%3}, {%4,%5,%6,%7}, {%8,%9}, {%0,%1,%2,%3};"
        : "+f"(c[0]), "+f"(c[1]), "+f"(c[2]), "+f"(c[3])
        : "r"(a.x), "r"(a.y), "r"(a.z), "r"(a.w), "r"(b0), "r"(b1));
}

__device__ __forceinline__ uint32_t smem_u32(const void* p) {
    uint32_t a;
    asm("{ .reg .u64 t; cvta.to.shared.u64 t, %1; cvt.u32.u64 %0, t; }" : "=r"(a) : "l"(p));
    return a;
}

// ---------------- main kernel: 8 compute warps + 8 producer warps ----------------
__global__ __launch_bounds__(512, 1)
void encoder_hmma_kernel(const float* __restrict__ x,
                         const float* __restrict__ ts,
                         const float* __restrict__ bias,
                         float* __restrict__ out) {
    extern __shared__ char smem[];
    const int tid  = threadIdx.x;
    const int lane = tid & 31;
    const int p0   = blockIdx.x * 128;
    const int b    = blockIdx.y;

    float* smed = (float*)(smem + OFF_SMED);
    float* cb   = (float*)(smem + OFF_CB);
    float* pe   = (float*)(smem + OFF_PE);

    const float* xb = x + (size_t)b * (L_ * 32);

    // producer-side macros use pid (0..255)
    const int pid = tid - 256;

    #define LOAD_X(XR) do {                                                   \
        _Pragma("unroll")                                                     \
        for (int i = 0; i < 16; i++) {                                        \
            int c2  = i >> 3;                                                 \
            int idx = pid + ((i & 7) << 8);                                   \
            int row = idx >> 4;                                               \
            int j2  = idx & 15;                                               \
            int p = p0 + row;                                                 \
            XR[i] = make_float2(0.f, 0.f);                                    \
            if (p < P_) XR[i] = *(const float2*)(xb + (size_t)p * 256 + (lxs * 2 + c2) * 32 + j2 * 2); \
        }                                                                     \
    } while (0)

    #define STS_A(BUF, XR) do {                                               \
        _Pragma("unroll")                                                     \
        for (int i = 0; i < 16; i++) {                                        \
            int c2  = i >> 3;                                                 \
            uint32_t* Ah = (uint32_t*)(smem + OFF_A(BUF, c2));                \
            int idx = pid + ((i & 7) << 8);                                   \
            int row = idx >> 4;                                               \
            int j2  = idx & 15;                                               \
            __half2 hv = __floats2half2_rn(XR[i].x, XR[i].y);                 \
            int mt = row >> 4, g = row & 7, rh = (row >> 3) & 1;              \
            int t = j2 & 3, ks = j2 >> 3, ch = (j2 >> 2) & 1;                 \
            int slot = (((ks << 3) + mt) * 32 + (g << 2) + t) * 4 + (ch << 1) + rh; \
            Ah[slot] = *(uint32_t*)&hv;                                       \
        }                                                                     \
    } while (0)

    #define CPASYNC_B(BUF, S) do {                                            \
        _Pragma("unroll")                                                     \
        for (int c2 = 0; c2 < 2; c2++) {                                      \
            uint32_t dst = smem_u32(smem + OFF_B(BUF, c2)) + pid * 16;        \
            const uint4* src = (const uint4*)(g_Bh + ((S) * 2 + c2) * 2048) + pid; \
            asm volatile("cp.async.ca.shared.global [%0], [%1], 16;"          \
                         :: "r"(dst), "l"(src));                              \
            asm volatile("cp.async.ca.shared.global [%0], [%1], 16;"          \
                         :: "r"(dst + 4096), "l"(src + 256));                 \
        }                                                                     \
    } while (0)

    #define COMMIT  asm volatile("cp.async.commit_group;")
    #define WAIT0   asm volatile("cp.async.wait_group 0;" ::: "memory")

    if (tid >= 256) {
        // ================= PRODUCER WARPS =================
        float2 xrA[16], xrB[16];
        int lxs;

        lxs = 0; LOAD_X(xrA);
        CPASYNC_B(0, 0); COMMIT;

        // medians + bias while chunk-0 x lands
        if (pid < 128) cb[pid] = bias[pid];
        if (pid < 128) {
            int p = p0 + pid;
            float med = 0.f;
            if (p < P_) {
                float v[KW];
                const float* tp = ts + b * L_ + p * STRIDE_;
                #pragma unroll
                for (int i = 0; i < KW; i++) v[i] = tp[i];
                #pragma unroll
                for (int pass = 0; pass < KW; pass++) {
                    int st = pass & 1;
                    #pragma unroll
                    for (int i = 0; i < KW - 1; i++) {
                        if ((i & 1) == st) {
                            float lo = fminf(v[i], v[i + 1]);
                            float hi = fmaxf(v[i], v[i + 1]);
                            v[i] = lo; v[i + 1] = hi;
                        }
                    }
                }
                med = v[(KW - 1) / 2];
            }
            smed[pid] = med;
        }
        STS_A(0, xrA);
        lxs = 1; LOAD_X(xrB);       // stage 1 x in flight
        WAIT0;
        __syncthreads();            // [sync 0] stage 0 ready

        #pragma unroll
        for (int s = 0; s < NST; s += 2) {
            // ---- stage s (even): compute consumes buf s&1; we stage s+1 ----
            {
                int nbuf = (s + 1) & 1;
                STS_A(nbuf, xrB);                       // stage s+1 frags (odd -> xrB)
                CPASYNC_B(nbuf, s + 1); COMMIT;
                if (s + 2 < NST) { lxs = s + 2; LOAD_X(xrA); }
                WAIT0;
            }
            __syncthreads();
            // ---- stage s+1 (odd): we stage s+2 (or fill PE at the end) ----
            {
                if (s + 2 < NST) {
                    int nbuf = (s + 2) & 1;
                    STS_A(nbuf, xrA);
                    CPASYNC_B(nbuf, s + 2); COMMIT;
                    if (s + 3 < NST) { lxs = s + 3; LOAD_X(xrB); }
                    WAIT0;
                } else {
                    // last stage: precompute PE table (bias + sin/cos)
                    int pl = pid >> 1, dh = pid & 1;
                    float med = smed[pl];
                    float* per = pe + pl * PE_STRIDE + dh * 64;
                    #pragma unroll
                    for (int j = 0; j < 32; j++) {
                        int i = dh * 32 + j;
                        float dt = __expf((float)i * -0.14391156831f);
                        float sn, cs;
                        __sincosf(med * dt, &sn, &cs);
                        per[2 * j]     = cb[2 * i] + sn;
                        per[2 * j + 1] = cb[2 * i + 1] + cs;
                    }
                }
            }
            __syncthreads();
        }
        // producers done (epilogue is compute-only)
    } else {
        // ================= COMPUTE WARPS =================
        const int wid = tid >> 5;
        const int wm  = wid >> 1;   // 0..3
        const int wn  = wid & 1;    // 0..1

        float acc[2][8][4];
        #pragma unroll
        for (int i = 0; i < 2; i++)
            #pragma unroll
            for (int j = 0; j < 8; j++)
                #pragma unroll
                for (int q = 0; q < 4; q++) acc[i][j][q] = 0.f;

        __syncthreads();            // [sync 0] stage 0 ready

        #pragma unroll
        for (int s = 0; s < NST; s++) {
            int buf = s & 1;
            #pragma unroll
            for (int c2 = 0; c2 < 2; c2++) {
                const uint4* Ah4 = (const uint4*)(smem + OFF_A(buf, c2));
                const uint4* Bh4 = (const uint4*)(smem + OFF_B(buf, c2));
                #pragma unroll
                for (int ks = 0; ks < 2; ks++) {
                    uint4 ah0 = Ah4[((ks << 3) + wm * 2 + 0) * 32 + lane];
                    uint4 ah1 = Ah4[((ks << 3) + wm * 2 + 1) * 32 + lane];
                    #pragma unroll
                    for (int ntp = 0; ntp < 4; ntp++) {
                        uint4 bb = Bh4[((ks << 3) + wn * 4 + ntp) * 32 + lane];
                        mma_f16(acc[0][2 * ntp],     ah0, bb.x, bb.y);
                        mma_f16(acc[1][2 * ntp],     ah1, bb.x, bb.y);
                        mma_f16(acc[0][2 * ntp + 1], ah0, bb.z, bb.w);
                        mma_f16(acc[1][2 * ntp + 1], ah1, bb.z, bb.w);
                    }
                }
            }
            __syncthreads();
        }

        // ---- epilogue: add precomputed PE table, store ----
        const int t = lane & 3, g = lane >> 2;
        #pragma unroll
        for (int mt = 0; mt < 2; mt++) {
            #pragma unroll
            for (int half = 0; half < 2; half++) {
                int prow = wm * 32 + mt * 16 + g + half * 8;
                int p = p0 + prow;
                if (p >= P_) continue;
                const float* per = pe + prow * PE_STRIDE;
                float* orow = out + ((size_t)b * P_ + p) * D_;
                #pragma unroll
                for (int nt = 0; nt < 8; nt++) {
                    int d0 = wn * 64 + nt * 8 + 2 * t;
                    float2 pv = *(const float2*)(per + d0);
                    float2 o;
                    o.x = acc[mt][nt][half * 2 + 0] + pv.x;
                    o.y = acc[mt][nt][half * 2 + 1] + pv.y;
                    *(float2*)(orow + d0) = o;
                }
            }
        }
    }
}

extern "C" void kernel_launch(void* const* d_in, const int* in_sizes, int n_in,
                              void* d_out, int out_size) {
    const float* x    = (const float*)d_in[0];
    const float* ts   = (const float*)d_in[1];
    const float* w    = (const float*)d_in[2];
    const float* bias = (const float*)d_in[3];
    float* out = (float*)d_out;

    prep_w_kernel<<<128, 256>>>(w);

    cudaFuncSetAttribute(encoder_hmma_kernel,
                         cudaFuncAttributeMaxDynamicSharedMemorySize, SM_TOTAL);
    dim3 grid(32, B_);
    encoder_hmma_kernel<<<grid, 512, SM_TOTAL>>>(x, ts, bias, out);
}

// round 11
// speedup vs baseline: 1.1704x; 1.1704x over previous
#include <cuda_runtime.h>
#include <cuda_fp16.h>
#include <cstdint>

// ---------------- problem constants ----------------
#define B_      32
#define L_      32768
#define KW      16
#define D_      128
#define STRIDE_ 8
#define P_      4095
#define NCH     16           // K chunks (32 fp32 each, total 512)

// ---------------- smem layout (bytes) ----------------
// B half-set resident: 8 chunks x 8KB = 64KB. Plus smed/cb.
#define OFF_SMED 65536
#define OFF_CB   66048
#define SM_TOTAL 66560

// ---------------- precomputed W fragments (fp16), 128KB total ----------------
// layout: [chunk(16)][ks(2)][ntp(8)][lane(32)][4 u32]  (u32 = fp16x2)
// kappa permutation of the reduction index (consistent on A and B sides):
//   b0 regs cover m = ks*16 + 4t + {0,1};  b1 regs cover m = ks*16 + 4t + {2,3}
__device__ uint32_t g_Bh[NCH * 2048];

__global__ void prep_w_kernel(const float* __restrict__ w) {
    int idx = blockIdx.x * 256 + threadIdx.x;       // 0..32767
    int r    = idx & 3;          // reg within uint4: {nt0.b0, nt0.b1, nt1.b0, nt1.b1}
    int lane = (idx >> 2) & 31;
    int ntp  = (idx >> 7) & 7;
    int ks   = (idx >> 10) & 1;
    int ci   = idx >> 11;        // chunk = conv tap k
    int nt   = ntp * 2 + (r >> 1);
    int breg = r & 1;
    int n = nt * 8 + (lane >> 2);                   // d row
    int t = lane & 3;
    int m0 = ks * 16 + 4 * t + 2 * breg;            // kappa-permuted m
    float v0 = w[n * 512 + m0 * 16 + ci];
    float v1 = w[n * 512 + (m0 + 1) * 16 + ci];
    __half2 h = __floats2half2_rn(v0, v1);
    g_Bh[idx] = *(uint32_t*)&h;
}

// ---------------- mma wrapper (fp16) ----------------
__device__ __forceinline__ void mma_f16(float* c, uint4 a, uint32_t b0, uint32_t b1) {
    asm volatile(
        "mma.sync.aligned.m16n8k16.row.col.f32.f16.f16.f32 "
        "{%0,%1,%2,%3}, {%4,%5,%6,%7}, {%8,%9}, {%0,%1,%2,%3};"
        : "+f"(c[0]), "+f"(c[1]), "+f"(c[2]), "+f"(c[3])
        : "r"(a.x), "r"(a.y), "r"(a.z), "r"(a.w), "r"(b0), "r"(b1));
}

__device__ __forceinline__ uint32_t smem_u32(const void* p) {
    uint32_t a;
    asm("{ .reg .u64 t; cvta.to.shared.u64 t, %1; cvt.u32.u64 %0, t; }" : "=r"(a) : "l"(p));
    return a;
}

__device__ __forceinline__ uint32_t h2pack(float a, float b) {
    __half2 h = __floats2half2_rn(a, b);
    return *(uint32_t*)&h;
}

// ---------------- main kernel ----------------
__global__ __launch_bounds__(256, 2)
void encoder_hmma_kernel(const float* __restrict__ x,
                         const float* __restrict__ ts,
                         const float* __restrict__ bias,
                         float* __restrict__ out) {
    extern __shared__ char smem[];
    const int tid  = threadIdx.x;
    const int lane = tid & 31;
    const int wid  = tid >> 5;
    const int wm   = wid >> 1;     // 0..3  (p rows of 32)
    const int wn   = wid & 1;      // 0..1  (d cols of 64)
    const int g    = lane >> 2;
    const int t    = lane & 3;
    const int p0   = blockIdx.x * 128;
    const int b    = blockIdx.y;

    float* smed = (float*)(smem + OFF_SMED);
    float* cb   = (float*)(smem + OFF_CB);
    const float* xb = x + (size_t)b * (L_ * 32);

    // B half fill: 64KB = 8 chunks of fragments (16 x 16B per thread)
    #define FILL_B(H) do {                                                    \
        uint32_t dst = smem_u32(smem) + tid * 16;                             \
        const uint4* src = (const uint4*)g_Bh + (H) * 4096 + tid;             \
        _Pragma("unroll")                                                     \
        for (int i = 0; i < 16; i++) {                                        \
            asm volatile("cp.async.ca.shared.global [%0], [%1], 16;"          \
                         :: "r"(dst + i * 4096), "l"(src + i * 256));         \
        }                                                                     \
        asm volatile("cp.async.commit_group;");                               \
    } while (0)

    FILL_B(0);

    // ---- bias + medians while B half 0 streams in ----
    if (tid < 128) cb[tid] = bias[tid];
    if (tid < 128) {
        int p = p0 + tid;
        float med = 0.f;
        if (p < P_) {
            float v[KW];
            const float* tp = ts + b * L_ + p * STRIDE_;
            #pragma unroll
            for (int i = 0; i < KW; i++) v[i] = tp[i];
            #pragma unroll
            for (int pass = 0; pass < KW; pass++) {
                int st = pass & 1;
                #pragma unroll
                for (int i = 0; i < KW - 1; i++) {
                    if ((i & 1) == st) {
                        float lo = fminf(v[i], v[i + 1]);
                        float hi = fmaxf(v[i], v[i + 1]);
                        v[i] = lo; v[i + 1] = hi;
                    }
                }
            }
            med = v[(KW - 1) / 2];
        }
        smed[tid] = med;
    }

    // ---- A base pointers: clamped to xb for p >= P_ (garbage rows never stored) ----
    const float* aptr[2][2];
    #pragma unroll
    for (int mt = 0; mt < 2; mt++)
        #pragma unroll
        for (int rh = 0; rh < 2; rh++) {
            int p = p0 + wm * 32 + mt * 16 + rh * 8 + g;
            aptr[mt][rh] = (p < P_) ? (xb + (size_t)(8 * p) * 32 + 4 * t) : xb;
        }

    float4 xa[2][2][2];   // [mt][ks][rh]

    #define LOADA(CI) do {                                                    \
        _Pragma("unroll")                                                     \
        for (int mt = 0; mt < 2; mt++)                                        \
            _Pragma("unroll")                                                 \
            for (int rh = 0; rh < 2; rh++) {                                  \
                const float* bp = aptr[mt][rh] + (CI) * 32;                   \
                xa[mt][0][rh] = *(const float4*)(bp);                         \
                xa[mt][1][rh] = *(const float4*)(bp + 16);                    \
            }                                                                 \
    } while (0)

    LOADA(0);

    float acc[2][8][4];
    #pragma unroll
    for (int i = 0; i < 2; i++)
        #pragma unroll
        for (int j = 0; j < 8; j++)
            #pragma unroll
            for (int q = 0; q < 4; q++) acc[i][j][q] = 0.f;

    asm volatile("cp.async.wait_group 0;" ::: "memory");
    __syncthreads();     // B half 0 + medians visible

    const uint4* Bs = (const uint4*)smem;

    // one chunk of compute against smem-chunk index SC (0..7)
    #define CHUNK(SC, PF_NEXT, NEXT_CI) do {                                  \
        uint4 frag[2][2];                                                     \
        _Pragma("unroll")                                                     \
        for (int mt = 0; mt < 2; mt++)                                        \
            _Pragma("unroll")                                                 \
            for (int ks = 0; ks < 2; ks++) {                                  \
                float4 lo = xa[mt][ks][0];                                    \
                float4 hi = xa[mt][ks][1];                                    \
                frag[mt][ks].x = h2pack(lo.x, lo.y);                          \
                frag[mt][ks].y = h2pack(hi.x, hi.y);                          \
                frag[mt][ks].z = h2pack(lo.z, lo.w);                          \
                frag[mt][ks].w = h2pack(hi.z, hi.w);                          \
            }                                                                 \
        if (PF_NEXT) LOADA(NEXT_CI);                                          \
        _Pragma("unroll")                                                     \
        for (int ks = 0; ks < 2; ks++) {                                      \
            const uint4* brow = Bs + ((SC) * 2 + ks) * 256 + wn * 128 + lane; \
            uint4 bb0 = brow[0];                                              \
            uint4 bb1 = brow[32];                                             \
            uint4 bb2 = brow[64];                                             \
            uint4 bb3 = brow[96];                                             \
            mma_f16(acc[0][0], frag[0][ks], bb0.x, bb0.y);                    \
            mma_f16(acc[1][0], frag[1][ks], bb0.x, bb0.y);                    \
            mma_f16(acc[0][1], frag[0][ks], bb0.z, bb0.w);                    \
            mma_f16(acc[1][1], frag[1][ks], bb0.z, bb0.w);                    \
            mma_f16(acc[0][2], frag[0][ks], bb1.x, bb1.y);                    \
            mma_f16(acc[1][2], frag[1][ks], bb1.x, bb1.y);                    \
            mma_f16(acc[0][3], frag[0][ks], bb1.z, bb1.w);                    \
            mma_f16(acc[1][3], frag[1][ks], bb1.z, bb1.w);                    \
            mma_f16(acc[0][4], frag[0][ks], bb2.x, bb2.y);                    \
            mma_f16(acc[1][4], frag[1][ks], bb2.x, bb2.y);                    \
            mma_f16(acc[0][5], frag[0][ks], bb2.z, bb2.w);                    \
            mma_f16(acc[1][5], frag[1][ks], bb2.z, bb2.w);                    \
            mma_f16(acc[0][6], frag[0][ks], bb3.x, bb3.y);                    \
            mma_f16(acc[1][6], frag[1][ks], bb3.x, bb3.y);                    \
            mma_f16(acc[0][7], frag[0][ks], bb3.z, bb3.w);                    \
            mma_f16(acc[1][7], frag[1][ks], bb3.z, bb3.w);                    \
        }                                                                     \
    } while (0)

    // ---- half 0: chunks 0..7 (no syncs) ----
    #pragma unroll 4
    for (int ci = 0; ci < 8; ci++) {
        CHUNK(ci, true, ci + 1);   // prefetch A for ci+1 (chunk 8 prefetched at ci=7)
    }

    // ---- refill B with half 1 ----
    __syncthreads();               // everyone done reading half 0
    FILL_B(1);
    asm volatile("cp.async.wait_group 0;" ::: "memory");
    __syncthreads();               // half 1 visible

    // ---- half 1: chunks 8..15 (no syncs) ----
    #pragma unroll 4
    for (int ci = 8; ci < NCH; ci++) {
        CHUNK(ci - 8, ci + 1 < NCH, ci + 1);
    }

    // ---- epilogue: bias + sinusoidal PE from median, write out ----
    {
        float dt[8];
        #pragma unroll
        for (int nt = 0; nt < 8; nt++) {
            int i = wn * 32 + nt * 4 + t;                // d0/2
            dt[nt] = __expf((float)i * -0.14391156831f); // -2*ln(10000)/128
        }
        #pragma unroll
        for (int mt = 0; mt < 2; mt++) {
            #pragma unroll
            for (int half = 0; half < 2; half++) {
                int prow = wm * 32 + mt * 16 + g + half * 8;
                int p = p0 + prow;
                if (p >= P_) continue;
                float med = smed[prow];
                float* orow = out + ((size_t)b * P_ + p) * D_;
                #pragma unroll
                for (int nt = 0; nt < 8; nt++) {
                    int d0 = wn * 64 + nt * 8 + 2 * t;
                    float sn, cs;
                    __sincosf(med * dt[nt], &sn, &cs);
                    float2 o;
                    o.x = acc[mt][nt][half * 2 + 0] + cb[d0] + sn;
                    o.y = acc[mt][nt][half * 2 + 1] + cb[d0 + 1] + cs;
                    *(float2*)(orow + d0) = o;
                }
            }
        }
    }
}

extern "C" void kernel_launch(void* const* d_in, const int* in_sizes, int n_in,
                              void* d_out, int out_size) {
    const float* x    = (const float*)d_in[0];
    const float* ts   = (const float*)d_in[1];
    const float* w    = (const float*)d_in[2];
    const float* bias = (const float*)d_in[3];
    float* out = (float*)d_out;

    prep_w_kernel<<<128, 256>>>(w);

    cudaFuncSetAttribute(encoder_hmma_kernel,
                         cudaFuncAttributeMaxDynamicSharedMemorySize, SM_TOTAL);
    dim3 grid(32, B_);
    encoder_hmma_kernel<<<grid, 256, SM_TOTAL>>>(x, ts, bias, out);
}

// round 12
// speedup vs baseline: 1.2728x; 1.0875x over previous
#include <cuda_runtime.h>
#include <cuda_fp16.h>
#include <cstdint>

// ---------------- problem constants ----------------
#define B_      32
#define L_      32768
#define KW      16
#define D_      128
#define STRIDE_ 8
#define P_      4095
#define NCH     16           // K chunks (32 fp32 each, total 512)

// ---------------- smem layout (bytes) ----------------
// B half-set: 8 chunks x 8KB = 64KB @0;  A: 2 bufs x 8KB @64KB; smed/cb after.
#define OFF_B    0
#define OFF_A    65536
#define OFF_SMED 81920
#define OFF_CB   82432
#define SM_TOTAL 82944

#define SWZ(a) ((a) ^ (((a) >> 3) & 0x70))

// ---------------- precomputed W fragments (fp16), 128KB total ----------------
// layout: [chunk(16)][ks(2)][ntp(8)][lane(32)][4 u32] (u32 = fp16x2)
// natural k-order to match ldmatrix A fragments:
//   b0 regs: m = ks*16 + 2t + {0,1};  b1 regs: m = ks*16 + 2t+8 + {0,1}
__device__ uint32_t g_Bh[NCH * 2048];

__global__ void prep_w_kernel(const float* __restrict__ w) {
    int idx = blockIdx.x * 256 + threadIdx.x;       // 0..32767
    int r    = idx & 3;          // {nt0.b0, nt0.b1, nt1.b0, nt1.b1}
    int lane = (idx >> 2) & 31;
    int ntp  = (idx >> 7) & 7;
    int ks   = (idx >> 10) & 1;
    int ci   = idx >> 11;        // chunk = conv tap k
    int nt   = ntp * 2 + (r >> 1);
    int breg = r & 1;
    int n = nt * 8 + (lane >> 2);                   // d row
    int t = lane & 3;
    int m0 = ks * 16 + 2 * t + 8 * breg;            // natural k-order
    float v0 = w[n * 512 + m0 * 16 + ci];
    float v1 = w[n * 512 + (m0 + 1) * 16 + ci];
    __half2 h = __floats2half2_rn(v0, v1);
    g_Bh[idx] = *(uint32_t*)&h;
}

// ---------------- wrappers ----------------
__device__ __forceinline__ void mma_f16(float* c, uint4 a, uint32_t b0, uint32_t b1) {
    asm volatile(
        "mma.sync.aligned.m16n8k16.row.col.f32.f16.f16.f32 "
        "{%0,%1,%2,%3}, {%4,%5,%6,%7}, {%8,%9}, {%0,%1,%2,%3};"
        : "+f"(c[0]), "+f"(c[1]), "+f"(c[2]), "+f"(c[3])
        : "r"(a.x), "r"(a.y), "r"(a.z), "r"(a.w), "r"(b0), "r"(b1));
}

__device__ __forceinline__ uint4 ldsm4(uint32_t addr) {
    uint4 v;
    asm volatile("ldmatrix.sync.aligned.m8n8.x4.shared.b16 {%0,%1,%2,%3}, [%4];"
                 : "=r"(v.x), "=r"(v.y), "=r"(v.z), "=r"(v.w) : "r"(addr));
    return v;
}

__device__ __forceinline__ uint32_t smem_u32(const void* p) {
    uint32_t a;
    asm("{ .reg .u64 t; cvta.to.shared.u64 t, %1; cvt.u32.u64 %0, t; }" : "=r"(a) : "l"(p));
    return a;
}

// ---------------- main kernel: 128 threads, 4 warps of 64p x 64d ----------------
__global__ __launch_bounds__(128, 2)
void encoder_hmma_kernel(const float* __restrict__ x,
                         const float* __restrict__ ts,
                         const float* __restrict__ bias,
                         float* __restrict__ out) {
    extern __shared__ char smem[];
    const int tid  = threadIdx.x;
    const int lane = tid & 31;
    const int wid  = tid >> 5;     // 0..3
    const int wm   = wid >> 1;     // 0..1  (64 p rows each)
    const int wn   = wid & 1;      // 0..1  (64 d cols each)
    const int t    = lane & 3;
    const int p0   = blockIdx.x * 128;
    const int b    = blockIdx.y;

    float* smed = (float*)(smem + OFF_SMED);
    float* cb   = (float*)(smem + OFF_CB);
    const char* xbc = (const char*)(x + (size_t)b * (L_ * 32));

    const uint32_t smemB = smem_u32(smem) + OFF_B;
    const uint32_t smemA = smem_u32(smem) + OFF_A;

    // ---- B half fill via cp.async (64KB; 512B per thread) ----
    #define FILL_B(H) do {                                                    \
        uint32_t dst = smemB + tid * 16;                                      \
        const uint4* srcp = (const uint4*)g_Bh + (H) * 4096 + tid;            \
        _Pragma("unroll")                                                     \
        for (int i2 = 0; i2 < 32; i2++) {                                     \
            asm volatile("cp.async.ca.shared.global [%0], [%1], 16;"          \
                         :: "r"(dst + i2 * 2048), "l"(srcp + i2 * 128));      \
        }                                                                     \
        asm volatile("cp.async.commit_group;");                               \
    } while (0)
    #define WAIT0 asm volatile("cp.async.wait_group 0;" ::: "memory")

    FILL_B(0);

    // ---- bias + medians (one p-row per thread) ----
    {
        cb[tid] = bias[tid];
        int p = p0 + tid;
        float med = 0.f;
        if (p < P_) {
            float v[KW];
            const float* tp = ts + b * L_ + p * STRIDE_;
            #pragma unroll
            for (int i = 0; i < KW; i++) v[i] = tp[i];
            #pragma unroll
            for (int pass = 0; pass < KW; pass++) {
                int st = pass & 1;
                #pragma unroll
                for (int i = 0; i < KW - 1; i++) {
                    if ((i & 1) == st) {
                        float lo = fminf(v[i], v[i + 1]);
                        float hi = fmaxf(v[i], v[i + 1]);
                        v[i] = lo; v[i + 1] = hi;
                    }
                }
            }
            med = v[(KW - 1) / 2];
        }
        smed[tid] = med;
    }

    // ---- A staging addressing ----
    // thread handles 8 float4s per chunk: fi = tid + 128*i; row = fi>>3 = r0+16i; j = tid&7
    const int r0 = tid >> 3;
    const int j  = tid & 7;
    uint32_t offA[8];     // byte offset into xbc (chunk adds ci*128)
    #pragma unroll
    for (int i = 0; i < 8; i++) {
        int p = p0 + r0 + 16 * i;
        offA[i] = (p < P_) ? ((uint32_t)p * 1024u + (uint32_t)j * 16u) : ((uint32_t)j * 16u);
    }
    const uint32_t sts_off = SWZ((uint32_t)(r0 * 64 + (j >> 1) * 16)) + (j & 1) * 8;

    // ---- LDSM source offsets (per warp operand (mt, ks)) ----
    uint32_t lds_off[2][4];
    {
        int row_l = wm * 64 + (lane & 7) + (lane & 8);       // + mt*16 below
        int cbyt  = (lane >> 4) << 4;                        // + ks*32 below
        #pragma unroll
        for (int ks = 0; ks < 2; ks++)
            #pragma unroll
            for (int mt = 0; mt < 4; mt++)
                lds_off[ks][mt] = SWZ((uint32_t)((row_l + mt * 16) * 64 + cbyt + ks * 32));
    }

    float4 xa[8];
    #define LOAD_X(CI) do {                                                   \
        _Pragma("unroll")                                                     \
        for (int i = 0; i < 8; i++)                                           \
            xa[i] = *(const float4*)(xbc + offA[i] + (CI) * 128);             \
    } while (0)

    #define STS_A(BUF) do {                                                   \
        uint32_t sb = smemA + (BUF) * 8192 + sts_off;                         \
        _Pragma("unroll")                                                     \
        for (int i = 0; i < 8; i++) {                                         \
            __half2 h0 = __floats2half2_rn(xa[i].x, xa[i].y);                 \
            __half2 h1 = __floats2half2_rn(xa[i].z, xa[i].w);                 \
            asm volatile("st.shared.v2.b32 [%0], {%1, %2};"                   \
                :: "r"(sb + i * 1024), "r"(*(uint32_t*)&h0), "r"(*(uint32_t*)&h1)); \
        }                                                                     \
    } while (0)

    float acc[4][8][4];
    #pragma unroll
    for (int i = 0; i < 4; i++)
        #pragma unroll
        for (int jj = 0; jj < 8; jj++)
            #pragma unroll
            for (int q = 0; q < 4; q++) acc[i][jj][q] = 0.f;

    const uint4* Bs = (const uint4*)(smem + OFF_B);

    #define COMPUTE(BUF, SC) do {                                             \
        uint32_t abase = smemA + (BUF) * 8192;                                \
        _Pragma("unroll")                                                     \
        for (int ks = 0; ks < 2; ks++) {                                      \
            uint4 af[4];                                                      \
            _Pragma("unroll")                                                 \
            for (int mt = 0; mt < 4; mt++) af[mt] = ldsm4(abase + lds_off[ks][mt]); \
            const uint4* brow = Bs + ((SC) * 2 + ks) * 256 + wn * 128 + lane; \
            uint4 bb0 = brow[0];                                              \
            uint4 bb1 = brow[32];                                             \
            uint4 bb2 = brow[64];                                             \
            uint4 bb3 = brow[96];                                             \
            _Pragma("unroll")                                                 \
            for (int mt = 0; mt < 4; mt++) {                                  \
                mma_f16(acc[mt][0], af[mt], bb0.x, bb0.y);                    \
                mma_f16(acc[mt][1], af[mt], bb0.z, bb0.w);                    \
                mma_f16(acc[mt][2], af[mt], bb1.x, bb1.y);                    \
                mma_f16(acc[mt][3], af[mt], bb1.z, bb1.w);                    \
                mma_f16(acc[mt][4], af[mt], bb2.x, bb2.y);                    \
                mma_f16(acc[mt][5], af[mt], bb2.z, bb2.w);                    \
                mma_f16(acc[mt][6], af[mt], bb3.x, bb3.y);                    \
                mma_f16(acc[mt][7], af[mt], bb3.z, bb3.w);                    \
            }                                                                 \
        }                                                                     \
    } while (0)

    // ---- prologue: stage chunks 0,1; chunk 2 in regs ----
    LOAD_X(0);
    STS_A(0);
    LOAD_X(1);
    STS_A(1);
    LOAD_X(2);
    WAIT0;               // B half 0 landed
    __syncthreads();     // A bufs + B + medians visible

    // ---- main loop ----
    #pragma unroll 2
    for (int ci = 0; ci < NCH; ci++) {
        if (ci == 8) { WAIT0; __syncthreads(); }     // B half 1 visible
        COMPUTE(ci & 1, ci & 7);
        __syncthreads();                             // everyone done with buf (ci&1)
        if (ci + 2 < NCH) STS_A(ci & 1);             // stage chunk ci+2
        if (ci + 3 < NCH) LOAD_X(ci + 3);            // LDGs in flight over next COMPUTE
        if (ci == 7) FILL_B(1);                      // refill B with chunks 8..15
    }

    // ---- epilogue: bias + sinusoidal PE from median ----
    {
        float dt[8];
        #pragma unroll
        for (int nt = 0; nt < 8; nt++) {
            int i = wn * 32 + nt * 4 + t;                // d0/2
            dt[nt] = __expf((float)i * -0.14391156831f); // -2*ln(10000)/128
        }
        const int g = lane >> 2;
        #pragma unroll
        for (int mt = 0; mt < 4; mt++) {
            #pragma unroll
            for (int half = 0; half < 2; half++) {
                int prow = wm * 64 + mt * 16 + g + half * 8;
                int p = p0 + prow;
                if (p >= P_) continue;
                float med = smed[prow];
                float* orow = out + ((size_t)b * P_ + p) * D_;
                #pragma unroll
                for (int nt = 0; nt < 8; nt++) {
                    int d0 = wn * 64 + nt * 8 + 2 * t;
                    float sn, cs;
                    __sincosf(med * dt[nt], &sn, &cs);
                    float2 o;
                    o.x = acc[mt][nt][half * 2 + 0] + cb[d0] + sn;
                    o.y = acc[mt][nt][half * 2 + 1] + cb[d0 + 1] + cs;
                    *(float2*)(orow + d0) = o;
                }
            }
        }
    }
}

extern "C" void kernel_launch(void* const* d_in, const int* in_sizes, int n_in,
                              void* d_out, int out_size) {
    const float* x    = (const float*)d_in[0];
    const float* ts   = (const float*)d_in[1];
    const float* w    = (const float*)d_in[2];
    const float* bias = (const float*)d_in[3];
    float* out = (float*)d_out;

    prep_w_kernel<<<128, 256>>>(w);

    cudaFuncSetAttribute(encoder_hmma_kernel,
                         cudaFuncAttributeMaxDynamicSharedMemorySize, SM_TOTAL);
    dim3 grid(32, B_);
    encoder_hmma_kernel<<<grid, 128, SM_TOTAL>>>(x, ts, bias, out);
}

// round 14
// speedup vs baseline: 1.3202x; 1.0372x over previous
#include <cuda_runtime.h>
#include <cuda_fp16.h>
#include <cstdint>

// ---------------- problem constants ----------------
#define B_      32
#define L_      32768
#define KW      16
#define D_      128
#define STRIDE_ 8
#define P_      4095
#define NCH     16           // K chunks (32 fp32 each, total 512)

// ---------------- smem layout (bytes) ----------------
// Full B resident: 16 chunks x 8KB = 128KB @0.
// A: 4 pairs x 2 bufs x 4KB = 32KB @128KB.  smed(256f), cb(128f) after.
#define OFF_B    0
#define OFF_A    131072
#define OFF_SMED 163840
#define OFF_CB   164864
#define SM_TOTAL 165376

#define SWZ(a) ((a) ^ (((a) >> 3) & 0x70))

// ---------------- precomputed W fragments (fp16), 128KB ----------------
// layout: [chunk(16)][ks(2)][ntp(8)][lane(32)][4 u32] (u32 = fp16x2)
// natural k-order: b0 regs: m = ks*16 + 2t + {0,1}; b1 regs: m = ks*16 + 2t+8 + {0,1}
__device__ uint32_t g_Bh[NCH * 2048];

__global__ void prep_w_kernel(const float* __restrict__ w) {
    int idx = blockIdx.x * 256 + threadIdx.x;       // 0..32767
    int r    = idx & 3;          // {nt0.b0, nt0.b1, nt1.b0, nt1.b1}
    int lane = (idx >> 2) & 31;
    int ntp  = (idx >> 7) & 7;
    int ks   = (idx >> 10) & 1;
    int ci   = idx >> 11;        // chunk = conv tap k
    int nt   = ntp * 2 + (r >> 1);
    int breg = r & 1;
    int n = nt * 8 + (lane >> 2);                   // d row
    int t = lane & 3;
    int m0 = ks * 16 + 2 * t + 8 * breg;
    float v0 = w[n * 512 + m0 * 16 + ci];
    float v1 = w[n * 512 + (m0 + 1) * 16 + ci];
    __half2 h = __floats2half2_rn(v0, v1);
    g_Bh[idx] = *(uint32_t*)&h;
}

// ---------------- wrappers ----------------
__device__ __forceinline__ void mma_f16(float* c, uint4 a, uint32_t b0, uint32_t b1) {
    asm volatile(
        "mma.sync.aligned.m16n8k16.row.col.f32.f16.f16.f32 "
        "{%0,%1,%2,%3}, {%4,%5,%6,%7}, {%8,%9}, {%0,%1,%2,%3};"
        : "+f"(c[0]), "+f"(c[1]), "+f"(c[2]), "+f"(c[3])
        : "r"(a.x), "r"(a.y), "r"(a.z), "r"(a.w), "r"(b0), "r"(b1));
}

__device__ __forceinline__ uint4 ldsm4(uint32_t addr) {
    uint4 v;
    asm volatile("ldmatrix.sync.aligned.m8n8.x4.shared.b16 {%0,%1,%2,%3}, [%4];"
                 : "=r"(v.x), "=r"(v.y), "=r"(v.z), "=r"(v.w) : "r"(addr));
    return v;
}

__device__ __forceinline__ uint32_t smem_u32(const void* p) {
    uint32_t a;
    asm("{ .reg .u64 t; cvta.to.shared.u64 t, %1; cvt.u32.u64 %0, t; }" : "=r"(a) : "l"(p));
    return a;
}

// ---------------- main kernel: 256 thr, 4x2 warps of 64p x 64d, 1 CTA/SM ----------------
__global__ __launch_bounds__(256, 1)
void encoder_hmma_kernel(const float* __restrict__ x,
                         const float* __restrict__ ts,
                         const float* __restrict__ bias,
                         float* __restrict__ out) {
    extern __shared__ char smem[];
    const int tid  = threadIdx.x;
    const int lane = tid & 31;
    const int wid  = tid >> 5;     // 0..7
    const int wm   = wid >> 1;     // 0..3  (64 p rows each)
    const int wn   = wid & 1;      // 0..1  (64 d cols each)
    const int t    = lane & 3;
    const int p0   = blockIdx.x * 256;
    const int b    = blockIdx.y;

    float* smed = (float*)(smem + OFF_SMED);
    float* cb   = (float*)(smem + OFF_CB);
    const char* xbc = (const char*)(x + (size_t)b * (L_ * 32));

    const uint32_t smemB = smem_u32(smem) + OFF_B;
    const uint32_t smemA = smem_u32(smem) + OFF_A + wm * 8192;   // pair-private

    // ---- fill ALL of B once (128KB; 512B per thread) ----
    {
        uint32_t dst = smemB + tid * 16;
        const uint4* srcp = (const uint4*)g_Bh + tid;
        #pragma unroll
        for (int i = 0; i < 32; i++) {
            asm volatile("cp.async.ca.shared.global [%0], [%1], 16;"
                         :: "r"(dst + i * 4096), "l"(srcp + i * 256));
        }
        asm volatile("cp.async.commit_group;");
    }

    // ---- bias + medians (one p-row per thread, 256 rows) ----
    {
        if (tid < 128) cb[tid] = bias[tid];
        int p = p0 + tid;
        float med = 0.f;
        if (p < P_) {
            float v[KW];
            const float* tp = ts + b * L_ + p * STRIDE_;
            #pragma unroll
            for (int i = 0; i < KW; i++) v[i] = tp[i];
            #pragma unroll
            for (int pass = 0; pass < KW; pass++) {
                int st = pass & 1;
                #pragma unroll
                for (int i = 0; i < KW - 1; i++) {
                    if ((i & 1) == st) {
                        float lo = fminf(v[i], v[i + 1]);
                        float hi = fmaxf(v[i], v[i + 1]);
                        v[i] = lo; v[i + 1] = hi;
                    }
                }
            }
            med = v[(KW - 1) / 2];
        }
        smed[tid] = med;
    }

    // ---- A staging addressing (pair-local) ----
    // pair thread pt=tid&63 handles 8 float4 per chunk: local row = (pt>>3)+8i, j = pt&7
    const int pt  = tid & 63;
    const int r0p = pt >> 3;
    const int j   = pt & 7;
    uint32_t offA[8];     // byte offset into xbc (chunk adds ci*128)
    #pragma unroll
    for (int i = 0; i < 8; i++) {
        int p = p0 + wm * 64 + r0p + 8 * i;
        offA[i] = (p < P_) ? ((uint32_t)p * 1024u + (uint32_t)j * 16u) : ((uint32_t)j * 16u);
    }
    const uint32_t sts_base = (uint32_t)(r0p * 64 + (j >> 1) * 16);
    const uint32_t sts_lo   = (uint32_t)((j & 1) * 8);

    // ---- LDSM source offsets (local rows 0..63) ----
    uint32_t lds_off[2][4];
    {
        int row_l = (lane & 7) + (lane & 8);
        int cbyt  = (lane >> 4) << 4;
        #pragma unroll
        for (int ks = 0; ks < 2; ks++)
            #pragma unroll
            for (int mt = 0; mt < 4; mt++)
                lds_off[ks][mt] = SWZ((uint32_t)((row_l + mt * 16) * 64 + cbyt + ks * 32));
    }

    float4 xa[8];
    #define LOAD_X(CI) do {                                                   \
        _Pragma("unroll")                                                     \
        for (int i = 0; i < 8; i++)                                           \
            xa[i] = *(const float4*)(xbc + offA[i] + (CI) * 128);             \
    } while (0)

    #define STS_A(BUF) do {                                                   \
        uint32_t sb = smemA + (BUF) * 4096;                                   \
        _Pragma("unroll")                                                     \
        for (int i = 0; i < 8; i++) {                                         \
            __half2 h0 = __floats2half2_rn(xa[i].x, xa[i].y);                 \
            __half2 h1 = __floats2half2_rn(xa[i].z, xa[i].w);                 \
            uint32_t ad = SWZ(sts_base + (uint32_t)(i * 512)) + sts_lo;       \
            asm volatile("st.shared.v2.b32 [%0], {%1, %2};"                   \
                :: "r"(sb + ad), "r"(*(uint32_t*)&h0), "r"(*(uint32_t*)&h1)); \
        }                                                                     \
    } while (0)

    // pair barrier: 2 warps (64 threads), id = wm+1
    #define BARP() asm volatile("bar.sync %0, 64;" :: "r"(wm + 1) : "memory")

    float acc[4][8][4];
    #pragma unroll
    for (int i = 0; i < 4; i++)
        #pragma unroll
        for (int jj = 0; jj < 8; jj++)
            #pragma unroll
            for (int q = 0; q < 4; q++) acc[i][jj][q] = 0.f;

    const uint4* Bs = (const uint4*)(smem + OFF_B);

    #define COMPUTE(BUF, CI) do {                                             \
        uint32_t abase = smemA + (BUF) * 4096;                                \
        _Pragma("unroll")                                                     \
        for (int ks = 0; ks < 2; ks++) {                                      \
            uint4 af[4];                                                      \
            _Pragma("unroll")                                                 \
            for (int mt = 0; mt < 4; mt++) af[mt] = ldsm4(abase + lds_off[ks][mt]); \
            const uint4* brow = Bs + ((CI) * 2 + ks) * 256 + wn * 128 + lane; \
            uint4 bb0 = brow[0];                                              \
            uint4 bb1 = brow[32];                                             \
            uint4 bb2 = brow[64];                                             \
            uint4 bb3 = brow[96];                                             \
            _Pragma("unroll")                                                 \
            for (int mt = 0; mt < 4; mt++) {                                  \
                mma_f16(acc[mt][0], af[mt], bb0.x, bb0.y);                    \
                mma_f16(acc[mt][1], af[mt], bb0.z, bb0.w);                    \
                mma_f16(acc[mt][2], af[mt], bb1.x, bb1.y);                    \
                mma_f16(acc[mt][3], af[mt], bb1.z, bb1.w);                    \
                mma_f16(acc[mt][4], af[mt], bb2.x, bb2.y);                    \
                mma_f16(acc[mt][5], af[mt], bb2.z, bb2.w);                    \
                mma_f16(acc[mt][6], af[mt], bb3.x, bb3.y);                    \
                mma_f16(acc[mt][7], af[mt], bb3.z, bb3.w);                    \
            }                                                                 \
        }                                                                     \
    } while (0)

    // ---- prologue: stage chunks 0,1; chunk 2 in regs ----
    LOAD_X(0);
    STS_A(0);
    LOAD_X(1);
    STS_A(1);
    LOAD_X(2);
    asm volatile("cp.async.wait_group 0;" ::: "memory");
    __syncthreads();     // B + A bufs + medians visible (ONLY CTA-wide sync)

    // ---- main loop: pair barriers only; tail barrier closes the race:
    //   partner STS_A(ci) -> partner BARP(ci+1) -> my COMPUTE(ci+2)
    //   (at ci+2==NCH the BARP-only arm provides the ordering for the last chunk)
    #pragma unroll 2
    for (int ci = 0; ci < NCH; ci++) {
        COMPUTE(ci & 1, ci);
        if (ci + 2 < NCH) {
            BARP();                        // pair done reading buf (ci&1)
            STS_A(ci & 1);                 // stage chunk ci+2
            if (ci + 3 < NCH) LOAD_X(ci + 3);
        } else if (ci + 2 == NCH) {
            BARP();                        // order partner's last STS_A before final COMPUTE
        }
    }

    // ---- epilogue: bias + sinusoidal PE from median ----
    {
        float dt[8];
        #pragma unroll
        for (int nt = 0; nt < 8; nt++) {
            int i = wn * 32 + nt * 4 + t;                // d0/2
            dt[nt] = __expf((float)i * -0.14391156831f); // -2*ln(10000)/128
        }
        const int g = lane >> 2;
        #pragma unroll
        for (int mt = 0; mt < 4; mt++) {
            #pragma unroll
            for (int half = 0; half < 2; half++) {
                int prow = wm * 64 + mt * 16 + g + half * 8;
                int p = p0 + prow;
                if (p >= P_) continue;
                float med = smed[prow];
                float* orow = out + ((size_t)b * P_ + p) * D_;
                #pragma unroll
                for (int nt = 0; nt < 8; nt++) {
                    int d0 = wn * 64 + nt * 8 + 2 * t;
                    float sn, cs;
                    __sincosf(med * dt[nt], &sn, &cs);
                    float2 o;
                    o.x = acc[mt][nt][half * 2 + 0] + cb[d0] + sn;
                    o.y = acc[mt][nt][half * 2 + 1] + cb[d0 + 1] + cs;
                    *(float2*)(orow + d0) = o;
                }
            }
        }
    }
}

extern "C" void kernel_launch(void* const* d_in, const int* in_sizes, int n_in,
                              void* d_out, int out_size) {
    const float* x    = (const float*)d_in[0];
    const float* ts   = (const float*)d_in[1];
    const float* w    = (const float*)d_in[2];
    const float* bias = (const float*)d_in[3];
    float* out = (float*)d_out;

    prep_w_kernel<<<128, 256>>>(w);

    cudaFuncSetAttribute(encoder_hmma_kernel,
                         cudaFuncAttributeMaxDynamicSharedMemorySize, SM_TOTAL);
    dim3 grid(16, B_);
    encoder_hmma_kernel<<<grid, 256, SM_TOTAL>>>(x, ts, bias, out);
}